// round 11
// baseline (speedup 1.0000x reference)
#include <cuda_runtime.h>
#include <cuda_bf16.h>
#include <math.h>

#define Bc 128
#define Pc 4096
#define Fc 32
#define Kc 8
#define Dc 64
#define ITERS_C 2

typedef unsigned long long ull;

// ---------------- scratch (static __device__, no runtime alloc) ----------------
__device__ ull g_kq[(size_t)Bc * 16 * Pc];     // K bf16 quads: [B][dquad 0..15][P]
__device__ ull g_vq[(size_t)Bc * Pc * 16];     // V bf16 quads: [B][P][dquad 0..15]
__device__ float g_slots[Bc * Kc * Dc];
__device__ float g_q[Bc * Kc * Dc];
__device__ float g_upd[Bc * Kc * Dc];
__device__ float g_S[Bc * Kc];
__device__ float g_WqT[Dc * Dc];               // [e][d]
__device__ float g_WihT[Dc * 3 * Dc];          // [e][j], stride 192
__device__ float g_WhhT[Dc * 3 * Dc];          // [e][j], stride 192
__device__ float g_W1T[Dc * 2 * Dc];           // [e][j], stride 128
__device__ float g_W2T[2 * Dc * Dc];           // [j][d], stride 64

// ---------------- packed helpers ----------------
__device__ __forceinline__ ull fma2(ull a, ull b, ull c) {
    ull d;
    asm("fma.rn.f32x2 %0, %1, %2, %3;" : "=l"(d) : "l"(a), "l"(b), "l"(c));
    return d;
}
__device__ __forceinline__ ull pack2(float x, float y) {
    ull r;
    asm("mov.b64 %0, {%1, %2};" : "=l"(r) : "f"(x), "f"(y));
    return r;
}
__device__ __forceinline__ float2 unpack2(ull v) {
    float2 r;
    asm("mov.b64 {%0, %1}, %2;" : "=f"(r.x), "=f"(r.y) : "l"(v));
    return r;
}
__device__ __forceinline__ unsigned bf2_of(float lo, float hi) {
    unsigned r;
    asm("cvt.rn.bf16x2.f32 %0, %1, %2;" : "=r"(r) : "f"(hi), "f"(lo));
    return r;
}
__device__ __forceinline__ ull packu(unsigned lo, unsigned hi) {
    ull r;
    asm("mov.b64 %0, {%1, %2};" : "=l"(r) : "r"(lo), "r"(hi));
    return r;
}
__device__ __forceinline__ void unpacku(ull v, unsigned& lo, unsigned& hi) {
    asm("mov.b64 {%0, %1}, %2;" : "=r"(lo), "=r"(hi) : "l"(v));
}
__device__ __forceinline__ float bflo(unsigned u) { return __uint_as_float(u << 16); }
__device__ __forceinline__ float bfhi(unsigned u) { return __uint_as_float(u & 0xffff0000u); }

// ---------------- init: slots init + weight transposes ----------------
__global__ void k_init(const float* __restrict__ noise, const float* __restrict__ mu,
                       const float* __restrict__ sigma, const float* __restrict__ Wq,
                       const float* __restrict__ Wih, const float* __restrict__ Whh,
                       const float* __restrict__ W1, const float* __restrict__ W2) {
    int i = blockIdx.x * blockDim.x + threadIdx.x;  // 0..65535
    if (i < Bc * Kc * Dc) {
        int d = i & 63;
        g_slots[i] = mu[d] + fabsf(sigma[d]) * noise[i];
    }
    if (i < Dc * Dc) {
        g_WqT[(i & 63) * Dc + (i >> 6)] = Wq[i];
    }
    if (i < 3 * Dc * Dc) {
        int j = i >> 6, e = i & 63;
        g_WihT[e * 192 + j] = Wih[i];
        g_WhhT[e * 192 + j] = Whh[i];
    }
    if (i < 2 * Dc * Dc) {
        int j = i >> 6, e = i & 63;
        g_W1T[e * 128 + j] = W1[i];
    }
    if (i < 2 * Dc * Dc) {
        int dd = i >> 7, j = i & 127;
        g_W2T[j * 64 + dd] = W2[i];
    }
}

// ---------------- q = LN(slots) @ Wq^T; zero S and upd (before iter 1) ----------------
__global__ void k_q(const float* __restrict__ lsg, const float* __restrict__ lsb) {
    int row = blockIdx.x;  // b*K+s
    int d = threadIdx.x;   // 0..63
    __shared__ float sh[64];
    __shared__ float red[2], red2[2];
    float v = g_slots[row * 64 + d];
    float s1 = v;
#pragma unroll
    for (int o = 16; o > 0; o >>= 1) s1 += __shfl_xor_sync(0xffffffffu, s1, o);
    if ((d & 31) == 0) red[d >> 5] = s1;
    __syncthreads();
    float mean = (red[0] + red[1]) * (1.f / 64.f);
    float dv = v - mean;
    float s2 = dv * dv;
#pragma unroll
    for (int o = 16; o > 0; o >>= 1) s2 += __shfl_xor_sync(0xffffffffu, s2, o);
    if ((d & 31) == 0) red2[d >> 5] = s2;
    __syncthreads();
    float var = (red2[0] + red2[1]) * (1.f / 64.f);
    float rstd = rsqrtf(var + 1e-5f);
    sh[d] = dv * rstd * lsg[d] + lsb[d];
    __syncthreads();
    float acc = 0.f;
#pragma unroll 8
    for (int e = 0; e < 64; e++) acc += sh[e] * g_WqT[e * 64 + d];
    g_q[row * 64 + d] = acc;
    g_upd[row * 64 + d] = 0.f;
    if (d == 0) g_S[row] = 0.f;
}

// ---------------- FUSED: LN(x) + K/V projection + iter-1 attention ----------------
// Computes k,v in registers; dots/softmax from fp32 k; S + unnormalized updates;
// writes bf16 kq/vq for iter 2. Never touches kq/vq as input -> saves 268MB DRAM.
// dynamic smem layout (16B aligned):
//   [0, 16384)         sW[32][128]   ([f][0..63]=WkT, [f][64..127]=WvT)
//   [16384, 16512)     sg[32]
//   [16512, 16640)     sb[32]
//   [16640, 18688)     sq2[32][8] ull (q pairs [dpair][slot])
//   [18688, 26880)     saf[256][8] float (attn, pixel-major)
//   [26880, 28928)     supd[512] float
//   [28928, 65792)     sv[256][18] ull (V staging, padded rows)
#define FUSED_SMEM 65792
__global__ void __launch_bounds__(256) k_projattn(const float* __restrict__ x,
                                                  const float* __restrict__ Wk,
                                                  const float* __restrict__ Wv,
                                                  const float* __restrict__ lg,
                                                  const float* __restrict__ lb) {
    extern __shared__ char dsm[];
    float (*sW)[128] = (float(*)[128])dsm;
    float* sg = (float*)(dsm + 16384);
    float* sb = (float*)(dsm + 16512);
    ull (*sq2)[8] = (ull(*)[8])(dsm + 16640);
    float (*saf)[8] = (float(*)[8])(dsm + 18688);
    float* supd = (float*)(dsm + 26880);
    ull* sv = (ull*)(dsm + 28928);

    int t = threadIdx.x;
    int b = blockIdx.x >> 4;
    int tile = blockIdx.x & 15;

    for (int i = t; i < Dc * Fc; i += 256) {
        int d = i >> 5, f = i & 31;
        sW[f][d] = Wk[i];
        sW[f][64 + d] = Wv[i];
    }
    if (t < Fc) { sg[t] = lg[t]; sb[t] = lb[t]; }
    {
        int dp = t >> 3, s = t & 7;
        sq2[dp][s] = pack2(g_q[b * 512 + s * 64 + 2 * dp],
                           g_q[b * 512 + s * 64 + 2 * dp + 1]);
    }
    supd[t] = 0.f;
    supd[t + 256] = 0.f;
    __syncthreads();

    int p = tile * 256 + t;
    size_t gp = (size_t)b * Pc + p;

    // ---- LayerNorm(x) ----
    float xv[32];
    {
        const float4* xr4 = (const float4*)(x + gp * Fc);
#pragma unroll
        for (int j = 0; j < 8; j++) {
            float4 q = xr4[j];
            xv[4 * j] = q.x; xv[4 * j + 1] = q.y; xv[4 * j + 2] = q.z; xv[4 * j + 3] = q.w;
        }
        float m = 0.f;
#pragma unroll
        for (int f = 0; f < 32; f++) m += xv[f];
        m *= (1.f / 32.f);
        float var = 0.f;
#pragma unroll
        for (int f = 0; f < 32; f++) { float dv = xv[f] - m; var += dv * dv; }
        float rstd = rsqrtf(var * (1.f / 32.f) + 1e-5f);
#pragma unroll
        for (int f = 0; f < 32; f++) xv[f] = (xv[f] - m) * rstd * sg[f] + sb[f];
    }

    // ---- K chunks (c=0,1): project, write bf16 kq, accumulate dots from fp32 k ----
    ull accd[8];
#pragma unroll
    for (int s = 0; s < 8; s++) accd[s] = 0ULL;
#pragma unroll
    for (int c = 0; c < 2; c++) {
        ull acc[16];
#pragma unroll
        for (int j = 0; j < 16; j++) acc[j] = 0ULL;
#pragma unroll 4
        for (int f = 0; f < 32; f++) {
            ull xx = pack2(xv[f], xv[f]);
            const ulonglong2* w2 = (const ulonglong2*)&sW[f][32 * c];
#pragma unroll
            for (int j = 0; j < 8; j++) {
                ulonglong2 wp = w2[j];
                acc[2 * j] = fma2(xx, wp.x, acc[2 * j]);
                acc[2 * j + 1] = fma2(xx, wp.y, acc[2 * j + 1]);
            }
        }
        // write kq (coalesced over p)
#pragma unroll
        for (int j = 0; j < 16; j += 2) {
            int q = 8 * c + (j >> 1);
            float2 r0 = unpack2(acc[j]);
            float2 r1 = unpack2(acc[j + 1]);
            g_kq[((size_t)b * 16 + q) * Pc + p] = packu(bf2_of(r0.x, r0.y), bf2_of(r1.x, r1.y));
        }
        // dots partial: acc[j] is k-pair for dp = 16*c + j
#pragma unroll
        for (int j = 0; j < 16; j++) {
            const ulonglong2* qa = (const ulonglong2*)sq2[16 * c + j];
#pragma unroll
            for (int jj = 0; jj < 4; jj++) {
                ulonglong2 av = qa[jj];
                accd[2 * jj] = fma2(acc[j], av.x, accd[2 * jj]);
                accd[2 * jj + 1] = fma2(acc[j], av.y, accd[2 * jj + 1]);
            }
        }
    }

    // ---- softmax over slots + eps ----
    float attn[8];
    {
        float mx = -1e30f;
#pragma unroll
        for (int s = 0; s < 8; s++) {
            float2 r = unpack2(accd[s]);
            attn[s] = (r.x + r.y) * 0.125f;
            mx = fmaxf(mx, attn[s]);
        }
        float sum = 0.f;
#pragma unroll
        for (int s = 0; s < 8; s++) { attn[s] = __expf(attn[s] - mx); sum += attn[s]; }
        float inv = 1.f / sum;
#pragma unroll
        for (int s = 0; s < 8; s++) attn[s] = attn[s] * inv + 1e-8f;
    }
    *(float4*)&saf[t][0] = make_float4(attn[0], attn[1], attn[2], attn[3]);
    *(float4*)&saf[t][4] = make_float4(attn[4], attn[5], attn[6], attn[7]);

    int w = t >> 5, lane = t & 31;
    // S via shfl butterfly
#pragma unroll
    for (int s = 0; s < 8; s++) {
        float v = attn[s];
#pragma unroll
        for (int o = 16; o > 0; o >>= 1) v += __shfl_xor_sync(0xffffffffu, v, o);
        if (lane == 0) atomicAdd(&g_S[b * Kc + s], v);
    }

    // ---- V chunks (c=2,3): project, stage bf16 quads in smem ----
#pragma unroll
    for (int c = 2; c < 4; c++) {
        ull acc[16];
#pragma unroll
        for (int j = 0; j < 16; j++) acc[j] = 0ULL;
#pragma unroll 4
        for (int f = 0; f < 32; f++) {
            ull xx = pack2(xv[f], xv[f]);
            const ulonglong2* w2 = (const ulonglong2*)&sW[f][32 * c];
#pragma unroll
            for (int j = 0; j < 8; j++) {
                ulonglong2 wp = w2[j];
                acc[2 * j] = fma2(xx, wp.x, acc[2 * j]);
                acc[2 * j + 1] = fma2(xx, wp.y, acc[2 * j + 1]);
            }
        }
        int qb = (c - 2) * 8;
#pragma unroll
        for (int j = 0; j < 16; j += 4) {
            float2 r0 = unpack2(acc[j]);
            float2 r1 = unpack2(acc[j + 1]);
            float2 r2 = unpack2(acc[j + 2]);
            float2 r3 = unpack2(acc[j + 3]);
            ulonglong2 qq;
            qq.x = packu(bf2_of(r0.x, r0.y), bf2_of(r1.x, r1.y));
            qq.y = packu(bf2_of(r2.x, r2.y), bf2_of(r3.x, r3.y));
            *(ulonglong2*)&sv[t * 18 + qb + (j >> 1)] = qq;
        }
    }
    __syncthreads();

    // ---- flush V to global (coalesced) ----
    ull* vout = (ull*)g_vq + ((size_t)b * Pc + tile * 256) * 16;
#pragma unroll
    for (int k = 0; k < 8; k++) {
        int i = t + 256 * k;          // 0..2047 ulonglong2
        int px = i >> 3, u = i & 7;
        ulonglong2 qq = *(const ulonglong2*)&sv[px * 18 + 2 * u];
        *(ulonglong2*)&vout[(size_t)px * 16 + 2 * u] = qq;
    }

    // ---- updates from smem v: warp w covers pixels p0..p0+31, lane = d-pair ----
    int p0 = w * 32;
    const unsigned* svu = (const unsigned*)sv;  // pixel stride = 36 unsigned (18 ull)
    ull ua[8];
#pragma unroll
    for (int s = 0; s < 8; s++) ua[s] = 0ULL;
#pragma unroll 8
    for (int i = 0; i < 32; i++) {
        unsigned u = svu[(p0 + i) * 36 + lane];   // bf162 for d = 2*lane, 2*lane+1
        ull v2 = pack2(bflo(u), bfhi(u));
        float4 a03 = *(const float4*)&saf[p0 + i][0];
        float4 a47 = *(const float4*)&saf[p0 + i][4];
        ua[0] = fma2(pack2(a03.x, a03.x), v2, ua[0]);
        ua[1] = fma2(pack2(a03.y, a03.y), v2, ua[1]);
        ua[2] = fma2(pack2(a03.z, a03.z), v2, ua[2]);
        ua[3] = fma2(pack2(a03.w, a03.w), v2, ua[3]);
        ua[4] = fma2(pack2(a47.x, a47.x), v2, ua[4]);
        ua[5] = fma2(pack2(a47.y, a47.y), v2, ua[5]);
        ua[6] = fma2(pack2(a47.z, a47.z), v2, ua[6]);
        ua[7] = fma2(pack2(a47.w, a47.w), v2, ua[7]);
    }
#pragma unroll
    for (int s = 0; s < 8; s++) {
        float2 r = unpack2(ua[s]);
        atomicAdd(&supd[s * 64 + 2 * lane], r.x);
        atomicAdd(&supd[s * 64 + 2 * lane + 1], r.y);
    }
    __syncthreads();
    atomicAdd(&g_upd[b * 512 + t], supd[t]);
    atomicAdd(&g_upd[b * 512 + t + 256], supd[t + 256]);
}

// ---------------- iter-2 attention (reads bf16 kq/vq), 2 px/thread ----------------
__global__ void __launch_bounds__(256) k_attn(float* __restrict__ out_attn, int last) {
    __shared__ ull sq2[32][8];
    __shared__ float saf[512][8];
    __shared__ float supd[512];
    int t = threadIdx.x;
    int b = blockIdx.x >> 3;
    int tile = blockIdx.x & 7;
    {
        int dp = t >> 3, s = t & 7;
        float q0 = g_q[b * 512 + s * 64 + 2 * dp];
        float q1 = g_q[b * 512 + s * 64 + 2 * dp + 1];
        sq2[dp][s] = pack2(q0, q1);
    }
    supd[t] = 0.f;
    supd[t + 256] = 0.f;
    __syncthreads();

    int px0 = tile * 512 + t;
    const ull* kb = g_kq + (size_t)b * 16 * Pc + px0;

    ull acc0[8], acc1[8];
#pragma unroll
    for (int s = 0; s < 8; s++) { acc0[s] = 0ULL; acc1[s] = 0ULL; }
#pragma unroll
    for (int q = 0; q < 16; q++) {
        ull kv0 = __ldg(kb + (size_t)q * Pc);
        ull kv1 = __ldg(kb + (size_t)q * Pc + 256);
        unsigned lo0, hi0, lo1, hi1;
        unpacku(kv0, lo0, hi0);
        unpacku(kv1, lo1, hi1);
        ull k0A = pack2(bflo(lo0), bfhi(lo0));
        ull k0B = pack2(bflo(hi0), bfhi(hi0));
        ull k1A = pack2(bflo(lo1), bfhi(lo1));
        ull k1B = pack2(bflo(hi1), bfhi(hi1));
        const ulonglong2* qa = (const ulonglong2*)sq2[2 * q];
        const ulonglong2* qb4 = (const ulonglong2*)sq2[2 * q + 1];
#pragma unroll
        for (int j = 0; j < 4; j++) {
            ulonglong2 av = qa[j];
            ulonglong2 bv = qb4[j];
            acc0[2 * j] = fma2(k0A, av.x, acc0[2 * j]);
            acc0[2 * j + 1] = fma2(k0A, av.y, acc0[2 * j + 1]);
            acc0[2 * j] = fma2(k0B, bv.x, acc0[2 * j]);
            acc0[2 * j + 1] = fma2(k0B, bv.y, acc0[2 * j + 1]);
            acc1[2 * j] = fma2(k1A, av.x, acc1[2 * j]);
            acc1[2 * j + 1] = fma2(k1A, av.y, acc1[2 * j + 1]);
            acc1[2 * j] = fma2(k1B, bv.x, acc1[2 * j]);
            acc1[2 * j + 1] = fma2(k1B, bv.y, acc1[2 * j + 1]);
        }
    }

    float attn0[8], attn1[8];
    {
        float mx = -1e30f;
#pragma unroll
        for (int s = 0; s < 8; s++) {
            float2 r = unpack2(acc0[s]);
            attn0[s] = (r.x + r.y) * 0.125f;
            mx = fmaxf(mx, attn0[s]);
        }
        float sum = 0.f;
#pragma unroll
        for (int s = 0; s < 8; s++) { attn0[s] = __expf(attn0[s] - mx); sum += attn0[s]; }
        float inv = 1.f / sum;
#pragma unroll
        for (int s = 0; s < 8; s++) attn0[s] = attn0[s] * inv + 1e-8f;
    }
    {
        float mx = -1e30f;
#pragma unroll
        for (int s = 0; s < 8; s++) {
            float2 r = unpack2(acc1[s]);
            attn1[s] = (r.x + r.y) * 0.125f;
            mx = fmaxf(mx, attn1[s]);
        }
        float sum = 0.f;
#pragma unroll
        for (int s = 0; s < 8; s++) { attn1[s] = __expf(attn1[s] - mx); sum += attn1[s]; }
        float inv = 1.f / sum;
#pragma unroll
        for (int s = 0; s < 8; s++) attn1[s] = attn1[s] * inv + 1e-8f;
    }

    *(float4*)&saf[t][0] = make_float4(attn0[0], attn0[1], attn0[2], attn0[3]);
    *(float4*)&saf[t][4] = make_float4(attn0[4], attn0[5], attn0[6], attn0[7]);
    *(float4*)&saf[t + 256][0] = make_float4(attn1[0], attn1[1], attn1[2], attn1[3]);
    *(float4*)&saf[t + 256][4] = make_float4(attn1[4], attn1[5], attn1[6], attn1[7]);

    if (last) {
        float* ao = out_attn + (size_t)b * Kc * Pc + px0;
#pragma unroll
        for (int s = 0; s < 8; s++) {
            ao[(size_t)s * Pc] = attn0[s];
            ao[(size_t)s * Pc + 256] = attn1[s];
        }
    }

    int w = t >> 5, lane = t & 31;
#pragma unroll
    for (int s = 0; s < 8; s++) {
        float v = attn0[s] + attn1[s];
#pragma unroll
        for (int o = 16; o > 0; o >>= 1) v += __shfl_xor_sync(0xffffffffu, v, o);
        if (lane == 0) atomicAdd(&g_S[b * Kc + s], v);
    }
    __syncthreads();

    int p0 = w * 64;
    const unsigned* vb = (const unsigned*)g_vq + ((size_t)b * Pc + tile * 512 + p0) * 32 + lane;
    ull ua[8];
#pragma unroll
    for (int s = 0; s < 8; s++) ua[s] = 0ULL;
#pragma unroll 8
    for (int i = 0; i < 64; i++) {
        unsigned u = __ldg(vb + i * 32);
        ull v2 = pack2(bflo(u), bfhi(u));
        float4 a03 = *(const float4*)&saf[p0 + i][0];
        float4 a47 = *(const float4*)&saf[p0 + i][4];
        ua[0] = fma2(pack2(a03.x, a03.x), v2, ua[0]);
        ua[1] = fma2(pack2(a03.y, a03.y), v2, ua[1]);
        ua[2] = fma2(pack2(a03.z, a03.z), v2, ua[2]);
        ua[3] = fma2(pack2(a03.w, a03.w), v2, ua[3]);
        ua[4] = fma2(pack2(a47.x, a47.x), v2, ua[4]);
        ua[5] = fma2(pack2(a47.y, a47.y), v2, ua[5]);
        ua[6] = fma2(pack2(a47.z, a47.z), v2, ua[6]);
        ua[7] = fma2(pack2(a47.w, a47.w), v2, ua[7]);
    }
#pragma unroll
    for (int s = 0; s < 8; s++) {
        float2 r = unpack2(ua[s]);
        atomicAdd(&supd[s * 64 + 2 * lane], r.x);
        atomicAdd(&supd[s * 64 + 2 * lane + 1], r.y);
    }
    __syncthreads();
    atomicAdd(&g_upd[b * 512 + t], supd[t]);
    atomicAdd(&g_upd[b * 512 + t + 256], supd[t + 256]);
}

// ---------------- GRU cell + LN + FF + residual (+ optional next-iter q) ----------------
__global__ void k_gru(const float* __restrict__ bih, const float* __restrict__ bhh,
                      const float* __restrict__ ffg, const float* __restrict__ ffb,
                      const float* __restrict__ fb1, const float* __restrict__ fb2,
                      const float* __restrict__ lsg, const float* __restrict__ lsb,
                      float* __restrict__ out_slots, int last) {
    int row = blockIdx.x;
    int d = threadIdx.x;
    __shared__ float su[64], sp[64], sf[64], sr1[128];
    __shared__ float red[2], red2[2];

    float S = g_S[row];
    float u = g_upd[row * 64 + d] / S;
    float hp = g_slots[row * 64 + d];
    su[d] = u;
    sp[d] = hp;
    __syncthreads();

    float gir = bih[d], giz = bih[64 + d], gin = bih[128 + d];
    float ghr = bhh[d], ghz = bhh[64 + d], ghn = bhh[128 + d];
#pragma unroll 4
    for (int e = 0; e < 64; e++) {
        float ue = su[e], he = sp[e];
        const float* wi = g_WihT + e * 192 + d;
        const float* wh = g_WhhT + e * 192 + d;
        gir += ue * wi[0];
        giz += ue * wi[64];
        gin += ue * wi[128];
        ghr += he * wh[0];
        ghz += he * wh[64];
        ghn += he * wh[128];
    }
    float r = 1.f / (1.f + expf(-(gir + ghr)));
    float z = 1.f / (1.f + expf(-(giz + ghz)));
    float n = tanhf(gin + r * ghn);
    float h = (1.f - z) * n + z * hp;

    float s1 = h;
#pragma unroll
    for (int o = 16; o > 0; o >>= 1) s1 += __shfl_xor_sync(0xffffffffu, s1, o);
    if ((d & 31) == 0) red[d >> 5] = s1;
    __syncthreads();
    float mean = (red[0] + red[1]) * (1.f / 64.f);
    float dv = h - mean;
    float s2 = dv * dv;
#pragma unroll
    for (int o = 16; o > 0; o >>= 1) s2 += __shfl_xor_sync(0xffffffffu, s2, o);
    if ((d & 31) == 0) red2[d >> 5] = s2;
    __syncthreads();
    float var = (red2[0] + red2[1]) * (1.f / 64.f);
    float rstd = rsqrtf(var + 1e-5f);
    sf[d] = dv * rstd * ffg[d] + ffb[d];
    __syncthreads();

    float a0 = fb1[d], a1 = fb1[64 + d];
#pragma unroll 8
    for (int e = 0; e < 64; e++) {
        float f = sf[e];
        a0 += f * g_W1T[e * 128 + d];
        a1 += f * g_W1T[e * 128 + 64 + d];
    }
    sr1[d] = fmaxf(a0, 0.f);
    sr1[64 + d] = fmaxf(a1, 0.f);
    __syncthreads();

    float o = fb2[d];
#pragma unroll 8
    for (int j = 0; j < 128; j++) o += sr1[j] * g_W2T[j * 64 + d];
    float ns = h + o;
    g_slots[row * 64 + d] = ns;
    if (last) {
        out_slots[row * 64 + d] = ns;
        return;
    }

    // fused: q for next iteration + reset accumulators
    float t1 = ns;
#pragma unroll
    for (int off = 16; off > 0; off >>= 1) t1 += __shfl_xor_sync(0xffffffffu, t1, off);
    if ((d & 31) == 0) red[d >> 5] = t1;
    __syncthreads();
    float qmean = (red[0] + red[1]) * (1.f / 64.f);
    float qdv = ns - qmean;
    float t2 = qdv * qdv;
#pragma unroll
    for (int off = 16; off > 0; off >>= 1) t2 += __shfl_xor_sync(0xffffffffu, t2, off);
    if ((d & 31) == 0) red2[d >> 5] = t2;
    __syncthreads();
    float qvar = (red2[0] + red2[1]) * (1.f / 64.f);
    float qrstd = rsqrtf(qvar + 1e-5f);
    sf[d] = qdv * qrstd * lsg[d] + lsb[d];
    __syncthreads();
    float qacc = 0.f;
#pragma unroll 8
    for (int e = 0; e < 64; e++) qacc += sf[e] * g_WqT[e * 64 + d];
    g_q[row * 64 + d] = qacc;
    g_upd[row * 64 + d] = 0.f;
    if (d == 0) g_S[row] = 0.f;
}

// ---------------- final attn normalization over pixels (vectorized) ----------------
__global__ void k_scale(float* __restrict__ out_attn) {
    size_t i = (size_t)blockIdx.x * 256 + threadIdx.x;
    int row = (int)((i * 4) >> 12);
    float inv = 1.f / g_S[row];
    float4* p4 = (float4*)out_attn;
    float4 v = p4[i];
    v.x *= inv; v.y *= inv; v.z *= inv; v.w *= inv;
    p4[i] = v;
}

// ---------------- launch ----------------
extern "C" void kernel_launch(void* const* d_in, const int* in_sizes, int n_in,
                              void* d_out, int out_size) {
    const float* x = (const float*)d_in[0];
    const float* noise = (const float*)d_in[1];
    const float* mu = (const float*)d_in[2];
    const float* sigma = (const float*)d_in[3];
    const float* Wq = (const float*)d_in[4];
    const float* Wk = (const float*)d_in[5];
    const float* Wv = (const float*)d_in[6];
    const float* Wih = (const float*)d_in[7];
    const float* Whh = (const float*)d_in[8];
    const float* bih = (const float*)d_in[9];
    const float* bhh = (const float*)d_in[10];
    const float* ling = (const float*)d_in[11];
    const float* linb = (const float*)d_in[12];
    const float* lsg = (const float*)d_in[13];
    const float* lsb = (const float*)d_in[14];
    const float* ffg = (const float*)d_in[15];
    const float* ffb = (const float*)d_in[16];
    const float* W1 = (const float*)d_in[17];
    const float* fb1 = (const float*)d_in[18];
    const float* W2 = (const float*)d_in[19];
    const float* fb2 = (const float*)d_in[20];

    float* out = (float*)d_out;
    float* out_slots = out;                     // [B,K,D]
    float* out_attn = out + Bc * Kc * Dc;       // [B,K,P]

    cudaFuncSetAttribute(k_projattn, cudaFuncAttributeMaxDynamicSharedMemorySize, FUSED_SMEM);

    k_init<<<256, 256>>>(noise, mu, sigma, Wq, Wih, Whh, W1, W2);
    k_q<<<Bc * Kc, 64>>>(lsg, lsb);
    // iter 1: fused projection + attention (no kq/vq re-read)
    k_projattn<<<(Bc * Pc) / 256, 256, FUSED_SMEM>>>(x, Wk, Wv, ling, linb);
    k_gru<<<Bc * Kc, 64>>>(bih, bhh, ffg, ffb, fb1, fb2, lsg, lsb, out_slots, 0);
    // iter 2: attention from stored bf16 k/v, writes last_attn
    k_attn<<<(Bc * Pc) / 512, 256>>>(out_attn, 1);
    k_gru<<<Bc * Kc, 64>>>(bih, bhh, ffg, ffb, fb1, fb2, lsg, lsb, out_slots, 1);
    k_scale<<<(Bc * Kc * Pc) / 1024, 256>>>(out_attn);
}

// round 12
// speedup vs baseline: 1.2758x; 1.2758x over previous
#include <cuda_runtime.h>
#include <cuda_bf16.h>
#include <math.h>

#define Bc 128
#define Pc 4096
#define Fc 32
#define Kc 8
#define Dc 64

typedef unsigned long long ull;

// ---------------- scratch (static __device__, no runtime alloc) ----------------
__device__ ull g_kq[(size_t)Bc * 16 * Pc];     // K bf16 quads: [B][dquad 0..15][P]
__device__ ull g_vq[(size_t)Bc * Pc * 16];     // V bf16 quads: [B][P][dquad 0..15]
__device__ float g_slots[Bc * Kc * Dc];
__device__ float g_q[Bc * Kc * Dc];
__device__ float g_upd[Bc * Kc * Dc];
__device__ float g_S[Bc * Kc];
__device__ __align__(16) float g_WqT[Dc * Dc];        // [e][d]
__device__ __align__(16) float g_WihT[Dc * 3 * Dc];   // [e][j], stride 192
__device__ __align__(16) float g_WhhT[Dc * 3 * Dc];   // [e][j], stride 192
__device__ __align__(16) float g_W1T[Dc * 2 * Dc];    // [e][j], stride 128
__device__ __align__(16) float g_W2T[2 * Dc * Dc];    // [j][d], stride 64

// ---------------- packed helpers ----------------
__device__ __forceinline__ ull fma2(ull a, ull b, ull c) {
    ull d;
    asm("fma.rn.f32x2 %0, %1, %2, %3;" : "=l"(d) : "l"(a), "l"(b), "l"(c));
    return d;
}
__device__ __forceinline__ ull pack2(float x, float y) {
    ull r;
    asm("mov.b64 %0, {%1, %2};" : "=l"(r) : "f"(x), "f"(y));
    return r;
}
__device__ __forceinline__ float2 unpack2(ull v) {
    float2 r;
    asm("mov.b64 {%0, %1}, %2;" : "=f"(r.x), "=f"(r.y) : "l"(v));
    return r;
}
__device__ __forceinline__ unsigned bf2_of(float lo, float hi) {
    unsigned r;
    asm("cvt.rn.bf16x2.f32 %0, %1, %2;" : "=r"(r) : "f"(hi), "f"(lo));
    return r;
}
__device__ __forceinline__ ull packu(unsigned lo, unsigned hi) {
    ull r;
    asm("mov.b64 %0, {%1, %2};" : "=l"(r) : "r"(lo), "r"(hi));
    return r;
}
__device__ __forceinline__ void unpacku(ull v, unsigned& lo, unsigned& hi) {
    asm("mov.b64 {%0, %1}, %2;" : "=r"(lo), "=r"(hi) : "l"(v));
}
__device__ __forceinline__ float bflo(unsigned u) { return __uint_as_float(u << 16); }
__device__ __forceinline__ float bfhi(unsigned u) { return __uint_as_float(u & 0xffff0000u); }

// ---------------- init: slots init + weight transposes ----------------
__global__ void k_init(const float* __restrict__ noise, const float* __restrict__ mu,
                       const float* __restrict__ sigma, const float* __restrict__ Wq,
                       const float* __restrict__ Wih, const float* __restrict__ Whh,
                       const float* __restrict__ W1, const float* __restrict__ W2) {
    int i = blockIdx.x * blockDim.x + threadIdx.x;  // 0..65535
    if (i < Bc * Kc * Dc) {
        int d = i & 63;
        g_slots[i] = mu[d] + fabsf(sigma[d]) * noise[i];
    }
    if (i < Dc * Dc) {
        g_WqT[(i & 63) * Dc + (i >> 6)] = Wq[i];
    }
    if (i < 3 * Dc * Dc) {
        int j = i >> 6, e = i & 63;
        g_WihT[e * 192 + j] = Wih[i];
        g_WhhT[e * 192 + j] = Whh[i];
    }
    if (i < 2 * Dc * Dc) {
        int j = i >> 6, e = i & 63;
        g_W1T[e * 128 + j] = W1[i];
    }
    if (i < 2 * Dc * Dc) {
        int dd = i >> 7, j = i & 127;
        g_W2T[j * 64 + dd] = W2[i];
    }
}

// ---------------- LayerNorm(x) + K/V projection (bf16 outputs), 1 px/thread ----------------
// (measured-best 385us config)
//   [0, 16384)         sW[32][128]
//   [16384, 16512)     sg[32]
//   [16512, 16640)     sb[32]
//   [16640, 53504)     sv[256][18] ull
#define PROJ_SMEM 53504
__global__ void __launch_bounds__(256) k_proj(const float* __restrict__ x,
                                              const float* __restrict__ Wk,
                                              const float* __restrict__ Wv,
                                              const float* __restrict__ lg,
                                              const float* __restrict__ lb) {
    extern __shared__ char dsm[];
    float (*sW)[128] = (float(*)[128])dsm;
    float* sg = (float*)(dsm + 16384);
    float* sb = (float*)(dsm + 16512);
    ull* sv = (ull*)(dsm + 16640);

    int t = threadIdx.x;
    for (int i = t; i < Dc * Fc; i += 256) {
        int d = i >> 5, f = i & 31;
        sW[f][d] = Wk[i];
        sW[f][64 + d] = Wv[i];
    }
    if (t < Fc) { sg[t] = lg[t]; sb[t] = lb[t]; }
    __syncthreads();

    size_t gpbase = (size_t)blockIdx.x * 256;
    size_t gp = gpbase + t;
    int b = (int)(gp >> 12);
    int p = (int)(gp & 4095);

    const float4* xr4 = (const float4*)(x + gp * Fc);
    float xv[32];
#pragma unroll
    for (int j = 0; j < 8; j++) {
        float4 q = xr4[j];
        xv[4 * j] = q.x; xv[4 * j + 1] = q.y; xv[4 * j + 2] = q.z; xv[4 * j + 3] = q.w;
    }
    float m = 0.f;
#pragma unroll
    for (int f = 0; f < 32; f++) m += xv[f];
    m *= (1.f / 32.f);
    float var = 0.f;
#pragma unroll
    for (int f = 0; f < 32; f++) { float dv = xv[f] - m; var += dv * dv; }
    var *= (1.f / 32.f);
    float rstd = rsqrtf(var + 1e-5f);
#pragma unroll
    for (int f = 0; f < 32; f++) xv[f] = (xv[f] - m) * rstd * sg[f] + sb[f];

#pragma unroll
    for (int c = 0; c < 4; c++) {
        ull acc[16];
#pragma unroll
        for (int j = 0; j < 16; j++) acc[j] = 0ULL;
#pragma unroll 4
        for (int f = 0; f < 32; f++) {
            ull xx = pack2(xv[f], xv[f]);
            const ulonglong2* w2 = (const ulonglong2*)&sW[f][32 * c];
#pragma unroll
            for (int j = 0; j < 8; j++) {
                ulonglong2 wp = w2[j];
                acc[2 * j] = fma2(xx, wp.x, acc[2 * j]);
                acc[2 * j + 1] = fma2(xx, wp.y, acc[2 * j + 1]);
            }
        }
        if (c < 2) {
#pragma unroll
            for (int j = 0; j < 16; j += 2) {
                float2 r0 = unpack2(acc[j]);
                float2 r1 = unpack2(acc[j + 1]);
                unsigned b0 = bf2_of(r0.x, r0.y);
                unsigned b1 = bf2_of(r1.x, r1.y);
                int q = 8 * c + (j >> 1);
                g_kq[((size_t)b * 16 + q) * Pc + p] = packu(b0, b1);
            }
        } else {
            int qb = (c - 2) * 8;
#pragma unroll
            for (int j = 0; j < 16; j += 4) {
                float2 r0 = unpack2(acc[j]);
                float2 r1 = unpack2(acc[j + 1]);
                float2 r2 = unpack2(acc[j + 2]);
                float2 r3 = unpack2(acc[j + 3]);
                ulonglong2 qq;
                qq.x = packu(bf2_of(r0.x, r0.y), bf2_of(r1.x, r1.y));
                qq.y = packu(bf2_of(r2.x, r2.y), bf2_of(r3.x, r3.y));
                *(ulonglong2*)&sv[t * 18 + qb + (j >> 1)] = qq;
            }
        }
    }
    __syncthreads();

    ull* vout = (ull*)g_vq + gpbase * 16;
#pragma unroll
    for (int k = 0; k < 8; k++) {
        int i = t + 256 * k;
        int px = i >> 3, u = i & 7;
        ulonglong2 qq = *(const ulonglong2*)&sv[px * 18 + 2 * u];
        *(ulonglong2*)&vout[(size_t)px * 16 + 2 * u] = qq;
    }
}

// ---------------- q = LN(slots) @ Wq^T, batched: 1 block/batch, 8 rows ----------------
// smem: [0,16384) sWq; [16384, 18432) sh[512]; [18432, +128) red[16], red2[16]
#define Q_SMEM 18560
__global__ void __launch_bounds__(512) k_q2(const float* __restrict__ lsg,
                                            const float* __restrict__ lsb) {
    extern __shared__ char qsm[];
    float* sWq = (float*)qsm;
    float* sh = (float*)(qsm + 16384);
    float* red = (float*)(qsm + 18432);
    float* red2 = red + 16;

    int t = threadIdx.x, b = blockIdx.x;
    {
        const float4* s4 = (const float4*)g_WqT;
        float4* d4 = (float4*)sWq;
        for (int i = t; i < 1024; i += 512) d4[i] = s4[i];
    }
    int r = t >> 6, d = t & 63, lane = t & 31, wir = (t >> 5) & 1;
    int row = b * 8 + r;
    float v = g_slots[row * 64 + d];
    float s1 = v;
#pragma unroll
    for (int o = 16; o > 0; o >>= 1) s1 += __shfl_xor_sync(0xffffffffu, s1, o);
    if (lane == 0) red[r * 2 + wir] = s1;
    __syncthreads();
    float mean = (red[r * 2] + red[r * 2 + 1]) * (1.f / 64.f);
    float dv = v - mean;
    float s2 = dv * dv;
#pragma unroll
    for (int o = 16; o > 0; o >>= 1) s2 += __shfl_xor_sync(0xffffffffu, s2, o);
    if (lane == 0) red2[r * 2 + wir] = s2;
    __syncthreads();
    float var = (red2[r * 2] + red2[r * 2 + 1]) * (1.f / 64.f);
    float rstd = rsqrtf(var + 1e-5f);
    sh[r * 64 + d] = dv * rstd * lsg[d] + lsb[d];
    __syncthreads();
    float acc = 0.f;
#pragma unroll 8
    for (int e = 0; e < 64; e++) acc += sh[r * 64 + e] * sWq[e * 64 + d];
    g_q[row * 64 + d] = acc;
    g_upd[row * 64 + d] = 0.f;
    if (d == 0) g_S[row] = 0.f;
}

// ---------------- attention (reads bf16 kq/vq), 2 px/thread (best measured) ----------------
__global__ void __launch_bounds__(256) k_attn(float* __restrict__ out_attn, int last) {
    __shared__ ull sq2[32][8];
    __shared__ float saf[512][8];
    __shared__ float supd[512];
    int t = threadIdx.x;
    int b = blockIdx.x >> 3;
    int tile = blockIdx.x & 7;
    {
        int dp = t >> 3, s = t & 7;
        float q0 = g_q[b * 512 + s * 64 + 2 * dp];
        float q1 = g_q[b * 512 + s * 64 + 2 * dp + 1];
        sq2[dp][s] = pack2(q0, q1);
    }
    supd[t] = 0.f;
    supd[t + 256] = 0.f;
    __syncthreads();

    int px0 = tile * 512 + t;
    const ull* kb = g_kq + (size_t)b * 16 * Pc + px0;

    ull acc0[8], acc1[8];
#pragma unroll
    for (int s = 0; s < 8; s++) { acc0[s] = 0ULL; acc1[s] = 0ULL; }
#pragma unroll
    for (int q = 0; q < 16; q++) {
        ull kv0 = __ldg(kb + (size_t)q * Pc);
        ull kv1 = __ldg(kb + (size_t)q * Pc + 256);
        unsigned lo0, hi0, lo1, hi1;
        unpacku(kv0, lo0, hi0);
        unpacku(kv1, lo1, hi1);
        ull k0A = pack2(bflo(lo0), bfhi(lo0));
        ull k0B = pack2(bflo(hi0), bfhi(hi0));
        ull k1A = pack2(bflo(lo1), bfhi(lo1));
        ull k1B = pack2(bflo(hi1), bfhi(hi1));
        const ulonglong2* qa = (const ulonglong2*)sq2[2 * q];
        const ulonglong2* qb4 = (const ulonglong2*)sq2[2 * q + 1];
#pragma unroll
        for (int j = 0; j < 4; j++) {
            ulonglong2 av = qa[j];
            ulonglong2 bv = qb4[j];
            acc0[2 * j] = fma2(k0A, av.x, acc0[2 * j]);
            acc0[2 * j + 1] = fma2(k0A, av.y, acc0[2 * j + 1]);
            acc0[2 * j] = fma2(k0B, bv.x, acc0[2 * j]);
            acc0[2 * j + 1] = fma2(k0B, bv.y, acc0[2 * j + 1]);
            acc1[2 * j] = fma2(k1A, av.x, acc1[2 * j]);
            acc1[2 * j + 1] = fma2(k1A, av.y, acc1[2 * j + 1]);
            acc1[2 * j] = fma2(k1B, bv.x, acc1[2 * j]);
            acc1[2 * j + 1] = fma2(k1B, bv.y, acc1[2 * j + 1]);
        }
    }

    float attn0[8], attn1[8];
    {
        float mx = -1e30f;
#pragma unroll
        for (int s = 0; s < 8; s++) {
            float2 r = unpack2(acc0[s]);
            attn0[s] = (r.x + r.y) * 0.125f;
            mx = fmaxf(mx, attn0[s]);
        }
        float sum = 0.f;
#pragma unroll
        for (int s = 0; s < 8; s++) { attn0[s] = __expf(attn0[s] - mx); sum += attn0[s]; }
        float inv = 1.f / sum;
#pragma unroll
        for (int s = 0; s < 8; s++) attn0[s] = attn0[s] * inv + 1e-8f;
    }
    {
        float mx = -1e30f;
#pragma unroll
        for (int s = 0; s < 8; s++) {
            float2 r = unpack2(acc1[s]);
            attn1[s] = (r.x + r.y) * 0.125f;
            mx = fmaxf(mx, attn1[s]);
        }
        float sum = 0.f;
#pragma unroll
        for (int s = 0; s < 8; s++) { attn1[s] = __expf(attn1[s] - mx); sum += attn1[s]; }
        float inv = 1.f / sum;
#pragma unroll
        for (int s = 0; s < 8; s++) attn1[s] = attn1[s] * inv + 1e-8f;
    }

    *(float4*)&saf[t][0] = make_float4(attn0[0], attn0[1], attn0[2], attn0[3]);
    *(float4*)&saf[t][4] = make_float4(attn0[4], attn0[5], attn0[6], attn0[7]);
    *(float4*)&saf[t + 256][0] = make_float4(attn1[0], attn1[1], attn1[2], attn1[3]);
    *(float4*)&saf[t + 256][4] = make_float4(attn1[4], attn1[5], attn1[6], attn1[7]);

    if (last) {
        float* ao = out_attn + (size_t)b * Kc * Pc + px0;
#pragma unroll
        for (int s = 0; s < 8; s++) {
            ao[(size_t)s * Pc] = attn0[s];
            ao[(size_t)s * Pc + 256] = attn1[s];
        }
    }

    int w = t >> 5, lane = t & 31;
#pragma unroll
    for (int s = 0; s < 8; s++) {
        float v = attn0[s] + attn1[s];
#pragma unroll
        for (int o = 16; o > 0; o >>= 1) v += __shfl_xor_sync(0xffffffffu, v, o);
        if (lane == 0) atomicAdd(&g_S[b * Kc + s], v);
    }
    __syncthreads();

    int p0 = w * 64;
    const unsigned* vb = (const unsigned*)g_vq + ((size_t)b * Pc + tile * 512 + p0) * 32 + lane;
    ull ua[8];
#pragma unroll
    for (int s = 0; s < 8; s++) ua[s] = 0ULL;
#pragma unroll 8
    for (int i = 0; i < 64; i++) {
        unsigned u = __ldg(vb + i * 32);
        ull v2 = pack2(bflo(u), bfhi(u));
        float4 a03 = *(const float4*)&saf[p0 + i][0];
        float4 a47 = *(const float4*)&saf[p0 + i][4];
        ua[0] = fma2(pack2(a03.x, a03.x), v2, ua[0]);
        ua[1] = fma2(pack2(a03.y, a03.y), v2, ua[1]);
        ua[2] = fma2(pack2(a03.z, a03.z), v2, ua[2]);
        ua[3] = fma2(pack2(a03.w, a03.w), v2, ua[3]);
        ua[4] = fma2(pack2(a47.x, a47.x), v2, ua[4]);
        ua[5] = fma2(pack2(a47.y, a47.y), v2, ua[5]);
        ua[6] = fma2(pack2(a47.z, a47.z), v2, ua[6]);
        ua[7] = fma2(pack2(a47.w, a47.w), v2, ua[7]);
    }
#pragma unroll
    for (int s = 0; s < 8; s++) {
        float2 r = unpack2(ua[s]);
        atomicAdd(&supd[s * 64 + 2 * lane], r.x);
        atomicAdd(&supd[s * 64 + 2 * lane + 1], r.y);
    }
    __syncthreads();
    atomicAdd(&g_upd[b * 512 + t], supd[t]);
    atomicAdd(&g_upd[b * 512 + t + 256], supd[t + 256]);
}

// ---------------- GRU + LN + FF + residual (+ next-iter q), batched with smem weights ----
// 1 block per batch, 512 threads = 8 rows x 64 d. All weights staged in smem once.
// smem: sWih 49152 @0 | sWhh 49152 @49152 | sW1 32768 @98304 | sW2 32768 @131072 |
//       sWq 16384 @163840 | su/sp/sf @180224 (512 f each) | sr1 (1024 f) | red/red2 (32 f)
#define GRU_SMEM 190592
__global__ void __launch_bounds__(512) k_gru2(const float* __restrict__ bih,
                                              const float* __restrict__ bhh,
                                              const float* __restrict__ ffg,
                                              const float* __restrict__ ffb,
                                              const float* __restrict__ fb1,
                                              const float* __restrict__ fb2,
                                              const float* __restrict__ lsg,
                                              const float* __restrict__ lsb,
                                              float* __restrict__ out_slots, int last) {
    extern __shared__ char gsm[];
    float* sWih = (float*)gsm;
    float* sWhh = (float*)(gsm + 49152);
    float* sW1 = (float*)(gsm + 98304);
    float* sW2 = (float*)(gsm + 131072);
    float* sWq = (float*)(gsm + 163840);
    float* su = (float*)(gsm + 180224);
    float* sp = su + 512;
    float* sf = sp + 512;
    float* sr1 = sf + 512;      // 1024 floats
    float* red = sr1 + 1024;    // 16
    float* red2 = red + 16;     // 16

    int t = threadIdx.x, b = blockIdx.x;
    {
        const float4* s4;
        float4* d4;
        s4 = (const float4*)g_WihT; d4 = (float4*)sWih;
        for (int i = t; i < 3072; i += 512) d4[i] = s4[i];
        s4 = (const float4*)g_WhhT; d4 = (float4*)sWhh;
        for (int i = t; i < 3072; i += 512) d4[i] = s4[i];
        s4 = (const float4*)g_W1T; d4 = (float4*)sW1;
        for (int i = t; i < 2048; i += 512) d4[i] = s4[i];
        s4 = (const float4*)g_W2T; d4 = (float4*)sW2;
        for (int i = t; i < 2048; i += 512) d4[i] = s4[i];
        s4 = (const float4*)g_WqT; d4 = (float4*)sWq;
        for (int i = t; i < 1024; i += 512) d4[i] = s4[i];
    }

    int r = t >> 6, d = t & 63, lane = t & 31, wir = (t >> 5) & 1;
    int row = b * 8 + r;

    float S = g_S[row];
    float u = g_upd[row * 64 + d] / S;
    float hp = g_slots[row * 64 + d];
    su[r * 64 + d] = u;
    sp[r * 64 + d] = hp;
    __syncthreads();

    float gir = bih[d], giz = bih[64 + d], gin = bih[128 + d];
    float ghr = bhh[d], ghz = bhh[64 + d], ghn = bhh[128 + d];
#pragma unroll 8
    for (int e = 0; e < 64; e++) {
        float ue = su[r * 64 + e], he = sp[r * 64 + e];
        const float* wi = sWih + e * 192 + d;
        const float* wh = sWhh + e * 192 + d;
        gir += ue * wi[0];
        giz += ue * wi[64];
        gin += ue * wi[128];
        ghr += he * wh[0];
        ghz += he * wh[64];
        ghn += he * wh[128];
    }
    float rr = 1.f / (1.f + expf(-(gir + ghr)));
    float z = 1.f / (1.f + expf(-(giz + ghz)));
    float n = tanhf(gin + rr * ghn);
    float h = (1.f - z) * n + z * hp;

    // LayerNorm(h) within row (2 warps)
    float s1 = h;
#pragma unroll
    for (int o = 16; o > 0; o >>= 1) s1 += __shfl_xor_sync(0xffffffffu, s1, o);
    if (lane == 0) red[r * 2 + wir] = s1;
    __syncthreads();
    float mean = (red[r * 2] + red[r * 2 + 1]) * (1.f / 64.f);
    float dv = h - mean;
    float s2 = dv * dv;
#pragma unroll
    for (int o = 16; o > 0; o >>= 1) s2 += __shfl_xor_sync(0xffffffffu, s2, o);
    if (lane == 0) red2[r * 2 + wir] = s2;
    __syncthreads();
    float var = (red2[r * 2] + red2[r * 2 + 1]) * (1.f / 64.f);
    float rstd = rsqrtf(var + 1e-5f);
    sf[r * 64 + d] = dv * rstd * ffg[d] + ffb[d];
    __syncthreads();

    // FF1 (+ReLU)
    float a0 = fb1[d], a1 = fb1[64 + d];
#pragma unroll 8
    for (int e = 0; e < 64; e++) {
        float f = sf[r * 64 + e];
        a0 += f * sW1[e * 128 + d];
        a1 += f * sW1[e * 128 + 64 + d];
    }
    sr1[r * 128 + d] = fmaxf(a0, 0.f);
    sr1[r * 128 + 64 + d] = fmaxf(a1, 0.f);
    __syncthreads();

    // FF2 + residual
    float o = fb2[d];
#pragma unroll 8
    for (int j = 0; j < 128; j++) o += sr1[r * 128 + j] * sW2[j * 64 + d];
    float ns = h + o;
    g_slots[row * 64 + d] = ns;
    if (last) {
        out_slots[row * 64 + d] = ns;
        return;
    }

    // fused: q for next iteration + reset accumulators
    float t1 = ns;
#pragma unroll
    for (int off = 16; off > 0; off >>= 1) t1 += __shfl_xor_sync(0xffffffffu, t1, off);
    if (lane == 0) red[r * 2 + wir] = t1;
    __syncthreads();
    float qmean = (red[r * 2] + red[r * 2 + 1]) * (1.f / 64.f);
    float qdv = ns - qmean;
    float t2 = qdv * qdv;
#pragma unroll
    for (int off = 16; off > 0; off >>= 1) t2 += __shfl_xor_sync(0xffffffffu, t2, off);
    if (lane == 0) red2[r * 2 + wir] = t2;
    __syncthreads();
    float qvar = (red2[r * 2] + red2[r * 2 + 1]) * (1.f / 64.f);
    float qrstd = rsqrtf(qvar + 1e-5f);
    sf[r * 64 + d] = qdv * qrstd * lsg[d] + lsb[d];
    __syncthreads();
    float qacc = 0.f;
#pragma unroll 8
    for (int e = 0; e < 64; e++) qacc += sf[r * 64 + e] * sWq[e * 64 + d];
    g_q[row * 64 + d] = qacc;
    g_upd[row * 64 + d] = 0.f;
    if (d == 0) g_S[row] = 0.f;
}

// ---------------- final attn normalization over pixels (vectorized) ----------------
__global__ void k_scale(float* __restrict__ out_attn) {
    size_t i = (size_t)blockIdx.x * 256 + threadIdx.x;
    int row = (int)((i * 4) >> 12);
    float inv = 1.f / g_S[row];
    float4* p4 = (float4*)out_attn;
    float4 v = p4[i];
    v.x *= inv; v.y *= inv; v.z *= inv; v.w *= inv;
    p4[i] = v;
}

// ---------------- launch ----------------
extern "C" void kernel_launch(void* const* d_in, const int* in_sizes, int n_in,
                              void* d_out, int out_size) {
    const float* x = (const float*)d_in[0];
    const float* noise = (const float*)d_in[1];
    const float* mu = (const float*)d_in[2];
    const float* sigma = (const float*)d_in[3];
    const float* Wq = (const float*)d_in[4];
    const float* Wk = (const float*)d_in[5];
    const float* Wv = (const float*)d_in[6];
    const float* Wih = (const float*)d_in[7];
    const float* Whh = (const float*)d_in[8];
    const float* bih = (const float*)d_in[9];
    const float* bhh = (const float*)d_in[10];
    const float* ling = (const float*)d_in[11];
    const float* linb = (const float*)d_in[12];
    const float* lsg = (const float*)d_in[13];
    const float* lsb = (const float*)d_in[14];
    const float* ffg = (const float*)d_in[15];
    const float* ffb = (const float*)d_in[16];
    const float* W1 = (const float*)d_in[17];
    const float* fb1 = (const float*)d_in[18];
    const float* W2 = (const float*)d_in[19];
    const float* fb2 = (const float*)d_in[20];

    float* out = (float*)d_out;
    float* out_slots = out;                     // [B,K,D]
    float* out_attn = out + Bc * Kc * Dc;       // [B,K,P]

    cudaFuncSetAttribute(k_proj, cudaFuncAttributeMaxDynamicSharedMemorySize, PROJ_SMEM);
    cudaFuncSetAttribute(k_q2, cudaFuncAttributeMaxDynamicSharedMemorySize, Q_SMEM);
    cudaFuncSetAttribute(k_gru2, cudaFuncAttributeMaxDynamicSharedMemorySize, GRU_SMEM);

    k_init<<<256, 256>>>(noise, mu, sigma, Wq, Wih, Whh, W1, W2);
    k_proj<<<(Bc * Pc) / 256, 256, PROJ_SMEM>>>(x, Wk, Wv, ling, linb);
    k_q2<<<Bc, 512, Q_SMEM>>>(lsg, lsb);
    // iter 1
    k_attn<<<(Bc * Pc) / 512, 256>>>(out_attn, 0);
    k_gru2<<<Bc, 512, GRU_SMEM>>>(bih, bhh, ffg, ffb, fb1, fb2, lsg, lsb, out_slots, 0);
    // iter 2
    k_attn<<<(Bc * Pc) / 512, 256>>>(out_attn, 1);
    k_gru2<<<Bc, 512, GRU_SMEM>>>(bih, bhh, ffg, ffb, fb1, fb2, lsg, lsb, out_slots, 1);
    k_scale<<<(Bc * Kc * Pc) / 1024, 256>>>(out_attn);
}